// round 13
// baseline (speedup 1.0000x reference)
#include <cuda_runtime.h>
#include <cuda_fp16.h>
#include <math.h>
#include <stdint.h>

// ---------------- problem constants ----------------
#define BATCH 2
#define T_    64
#define H_    32
#define W_    32
#define C_    192
#define L_    (T_*H_*W_)
#define ROWS  (BATCH*L_)        // 131072 rows
#define NH_   6
#define HD_   32
#define NTOK  128
#define NWIN  512
#define C3    576
#define CM_   768
#define SCALE_ 0.17677669529663687f

// ---------------- scratch ----------------
__device__ __half g_act_hi[(size_t)ROWS * C_];
__device__ __half g_act_lo[(size_t)ROWS * C_];
__device__ __half g_hid_hi[(size_t)ROWS * CM_];
__device__ __half g_qkvh [(size_t)ROWS * C3];
__device__ float  g_x2   [(size_t)ROWS * C_];
__device__ __half g_w    [442368];

// ---------------- helpers ----------------
__device__ __forceinline__ uint32_t smem_u32(const void* p) {
    uint32_t a;
    asm("{ .reg .u64 t; cvta.to.shared.u64 t, %1; cvt.u32.u64 %0, t; }" : "=r"(a) : "l"(p));
    return a;
}
#define CPA16(dst, src) asm volatile("cp.async.cg.shared.global [%0], [%1], 16;" :: "r"(dst), "l"(src))
#define CPA_COMMIT()    asm volatile("cp.async.commit_group;" ::: "memory")
#define CPA_WAIT0()     asm volatile("cp.async.wait_group 0;" ::: "memory")
#define CPA_WAIT2()     asm volatile("cp.async.wait_group 2;" ::: "memory")
#define LDM4(d0,d1,d2,d3,addr) \
    asm volatile("ldmatrix.sync.aligned.m8n8.x4.shared.b16 {%0,%1,%2,%3}, [%4];" \
        : "=r"(d0), "=r"(d1), "=r"(d2), "=r"(d3) : "r"(addr))
#define LDM4T(d0,d1,d2,d3,addr) \
    asm volatile("ldmatrix.sync.aligned.m8n8.x4.trans.shared.b16 {%0,%1,%2,%3}, [%4];" \
        : "=r"(d0), "=r"(d1), "=r"(d2), "=r"(d3) : "r"(addr))

__device__ __forceinline__ void mma_f16(float* c, const uint32_t* a, const uint32_t* b) {
    asm volatile("mma.sync.aligned.m16n8k16.row.col.f32.f16.f16.f32 "
        "{%0,%1,%2,%3},{%4,%5,%6,%7},{%8,%9},{%0,%1,%2,%3};"
        : "+f"(c[0]), "+f"(c[1]), "+f"(c[2]), "+f"(c[3])
        : "r"(a[0]), "r"(a[1]), "r"(a[2]), "r"(a[3]), "r"(b[0]), "r"(b[1]));
}

__device__ __forceinline__ size_t shifted_pos(int row) {
    int win = row >> 7, n = row & 127;
    int b  = win >> 9, widx = win & 511;
    int tb = widx >> 6, hb = (widx >> 3) & 7, wb = widx & 7;
    int ti = n >> 4,   hi = (n >> 2) & 3,    wi = n & 3;
    int t  = (tb*8 + ti + 4) & 63;
    int hh = (hb*4 + hi + 2) & 31;
    int ww = (wb*4 + wi + 2) & 31;
    return (size_t)b * L_ + (size_t)t * (H_*W_) + hh * W_ + ww;
}

__device__ __forceinline__ void split_f16(float v, __half& h, __half& l) {
    h = __float2half_rn(v);
    l = __float2half_rn(v - __half2float(h));
}

// swizzled smem offset for a (row, 16B-chunk) pair, 32B logical rows, zero padding.
__device__ __forceinline__ uint32_t swz(int row, int ch) {
    return (uint32_t)(row * 32 + ((((row >> 2) & 1) ^ ch) << 4));
}

// ---------------- weight convert+transpose (all 4 weights) ----------------
__global__ void k_wconv_all(const float* __restrict__ qkv_w, const float* __restrict__ proj_w,
                            const float* __restrict__ fc1_w, const float* __restrict__ fc2_w,
                            __half* __restrict__ w) {
    int idx = blockIdx.x * 256 + threadIdx.x;
    if (idx >= 442368) return;
    const float* W; int K, N, off;
    if (idx < 110592)      { W = qkv_w;  K = 192; N = 576; off = 0; }
    else if (idx < 147456) { W = proj_w; K = 192; N = 192; off = 110592; }
    else if (idx < 294912) { W = fc1_w;  K = 192; N = 768; off = 147456; }
    else                   { W = fc2_w;  K = 768; N = 192; off = 294912; }
    int u = idx - off;
    int n = u / K, k = u - n * K;
    w[idx] = __float2half_rn(W[(size_t)k * N + n]);
}

// ---------------- layernorm -> fp16 hi/lo ----------------
template<bool SHIFTMAP>
__global__ void k_ln(const float* __restrict__ x, const float* __restrict__ g,
                     const float* __restrict__ bt,
                     __half* __restrict__ ohi, __half* __restrict__ olo) {
    int r = blockIdx.x;
    int c = threadIdx.x;
    size_t src = SHIFTMAP ? shifted_pos(r) * C_ : (size_t)r * C_;
    float v = x[src + c];
    float s1 = v, s2 = v * v;
    #pragma unroll
    for (int off = 16; off; off >>= 1) {
        s1 += __shfl_down_sync(0xffffffffu, s1, off);
        s2 += __shfl_down_sync(0xffffffffu, s2, off);
    }
    __shared__ float red[12];
    int warp = c >> 5, lane = c & 31;
    if (lane == 0) { red[warp] = s1; red[6 + warp] = s2; }
    __syncthreads();
    if (c == 0) {
        float a = 0.f, bb = 0.f;
        #pragma unroll
        for (int w2 = 0; w2 < 6; w2++) { a += red[w2]; bb += red[6 + w2]; }
        red[0] = a; red[6] = bb;
    }
    __syncthreads();
    float mu   = red[0] * (1.0f / 192.0f);
    float var  = red[6] * (1.0f / 192.0f) - mu * mu;
    float rstd = rsqrtf(var + 1e-5f);
    float y = (v - mu) * rstd * g[c] + bt[c];
    __half h, l; split_f16(y, h, l);
    ohi[(size_t)r * C_ + c] = h;
    olo[(size_t)r * C_ + c] = l;
}

// ---------------- A-resident GEMM (K=192): CTA = 128 rows x ALL N, A in smem, B double-buffered ----------------
// smem: Ahi [12 chunks x 128 x 32B] 48KB, Alo 48KB, B 2 x [12 chunks x 96 x 32B] 2x36KB = 168KB dynamic.
// MODE 0: ohi = half(A*B + bias)                (qkv, NT=6)
// MODE 1: outf[pos] = res[pos] + A*B + bias     (proj + reverse + roll + residual, NT=2)
// MODE 2: ohi = half(gelu(A*B + bias))          (fc1, NT=8)
template<int MODE, int NT>
__global__ __launch_bounds__(256, 1) void k_gemm_ares(
    const __half* __restrict__ Ahi, const __half* __restrict__ Alo,
    const __half* __restrict__ Bw, const float* __restrict__ bias,
    float* __restrict__ outf, __half* __restrict__ ohi,
    const float* __restrict__ res)
{
    extern __shared__ __align__(16) uint8_t smem[];
    const int tid = threadIdx.x;
    const int bm = blockIdx.x * 128;
    const uint32_t aH = smem_u32(smem);
    const uint32_t aL = aH + 49152;
    const uint32_t bB = aH + 98304;

    // ---- stage A (hi+lo) fully: 128 rows x 192 K ----
    #pragma unroll
    for (int i = 0; i < 12; i++) {
        int u = i * 256 + tid;          // 3072 (chunk, row, half16) slots
        int cch = u >> 8;
        int row = (u >> 1) & 127;
        int h = u & 1;
        uint32_t d = (uint32_t)(cch * 4096) + swz(row, h);
        size_t gs = (size_t)(bm + row) * 192 + cch * 16 + h * 8;
        CPA16(aH + d, Ahi + gs);
        CPA16(aL + d, Alo + gs);
    }
    CPA_COMMIT();

    auto load_B = [&](int nt, int s) {
        const __half* bp = Bw + (size_t)(nt * 96) * 192;
        uint32_t base = bB + (uint32_t)(s * 36864);
        #pragma unroll
        for (int i = 0; i < 9; i++) {
            int u = i * 256 + tid;      // 2304 slots
            int cch = u / 192;
            int v = u - cch * 192;
            int row = v >> 1, h = v & 1;
            CPA16(base + (uint32_t)(cch * 3072) + swz(row, h),
                  bp + (size_t)row * 192 + cch * 16 + h * 8);
        }
        CPA_COMMIT();
    };

    load_B(0, 0);
    CPA_WAIT0();
    __syncthreads();

    const int wid = tid >> 5, lane = tid & 31;
    const int wm = wid & 3, wn = wid >> 2;
    const int arow0 = wm * 32 + (lane & 15);
    const int ach = lane >> 4;
    const int g = lane >> 3;
    const int brow0 = wn * 48 + ((g >> 1) << 3) + (lane & 7);
    const int bch = g & 1;

    #pragma unroll 1
    for (int nt = 0; nt < NT; nt++) {
        const int s = nt & 1;
        if (nt + 1 < NT) load_B(nt + 1, s ^ 1);

        float acc[2][6][4] = {};
        const uint32_t bbase = bB + (uint32_t)(s * 36864);
        #pragma unroll
        for (int c = 0; c < 12; c++) {
            uint32_t ah[2][4], al[2][4], bh[3][4];
            #pragma unroll
            for (int mt = 0; mt < 2; mt++) {
                uint32_t ad = (uint32_t)(c * 4096) + swz(arow0 + mt * 16, ach);
                LDM4(ah[mt][0], ah[mt][1], ah[mt][2], ah[mt][3], aH + ad);
                LDM4(al[mt][0], al[mt][1], al[mt][2], al[mt][3], aL + ad);
            }
            #pragma unroll
            for (int p = 0; p < 3; p++) {
                uint32_t bd = bbase + (uint32_t)(c * 3072) + swz(brow0 + p * 16, bch);
                LDM4(bh[p][0], bh[p][1], bh[p][2], bh[p][3], bB + (bd - bB));
            }
            #pragma unroll
            for (int mt = 0; mt < 2; mt++)
                #pragma unroll
                for (int p = 0; p < 3; p++)
                    #pragma unroll
                    for (int q = 0; q < 2; q++) {
                        float* d = acc[mt][p * 2 + q];
                        mma_f16(d, ah[mt], &bh[p][q * 2]);
                        mma_f16(d, al[mt], &bh[p][q * 2]);
                    }
        }

        // ---- epilogue for columns [nt*96, nt*96+96) ----
        const int bn = nt * 96;
        const float* biasp = bias + bn;
        #pragma unroll
        for (int mt = 0; mt < 2; mt++) {
            #pragma unroll
            for (int ro = 0; ro < 2; ro++) {
                int grow = bm + wm * 32 + mt * 16 + (lane >> 2) + ro * 8;
                size_t dstbase;
                if (MODE == 1) dstbase = shifted_pos(grow) * (size_t)192;
                else           dstbase = (size_t)grow * (NT * 96);
                #pragma unroll
                for (int nc = 0; nc < 6; nc++) {
                    int col = wn * 48 + nc * 8 + (lane & 3) * 2;
                    float v0 = acc[mt][nc][ro * 2 + 0] + __ldg(biasp + col);
                    float v1 = acc[mt][nc][ro * 2 + 1] + __ldg(biasp + col + 1);
                    size_t oi = dstbase + bn + col;
                    if (MODE == 0) {
                        *(__half2*)&ohi[oi] = __halves2half2(__float2half_rn(v0), __float2half_rn(v1));
                    } else if (MODE == 2) {
                        v0 = 0.5f * v0 * (1.0f + erff(v0 * 0.70710678118654752f));
                        v1 = 0.5f * v1 * (1.0f + erff(v1 * 0.70710678118654752f));
                        *(__half2*)&ohi[oi] = __halves2half2(__float2half_rn(v0), __float2half_rn(v1));
                    } else {
                        float2 rv = *(const float2*)&res[oi];
                        float2 v; v.x = rv.x + v0; v.y = rv.y + v1;
                        *(float2*)&outf[oi] = v;
                    }
                }
            }
        }
        CPA_WAIT0();
        __syncthreads();
    }
}

// ---------------- 4-stage pipelined GEMM (kept for fc2, K=768, single-A) ----------------
// MODE 3: outf = res + A*B + bias
template<int MODE, bool SPLITA>
__global__ __launch_bounds__(256, 2) void k_mma_gemm(
    const __half* __restrict__ Ahi, const __half* __restrict__ Alo,
    const __half* __restrict__ Bw,
    const float* __restrict__ bias, int K, int Ntot,
    float* __restrict__ outf,
    __half* __restrict__ ohi, __half* __restrict__ olo,
    const float* __restrict__ res)
{
    __shared__ __align__(16) uint8_t sAh[4 * 128 * 32];
    __shared__ __align__(16) uint8_t sAl[4 * 128 * 32];
    __shared__ __align__(16) uint8_t sBh[4 * 96 * 32];

    const int tid = threadIdx.x;
    const int wid = tid >> 5, lane = tid & 31;
    const int wm = wid & 3, wn = wid >> 2;
    const int bm = blockIdx.y * 128;
    const int bn = blockIdx.x * 96;
    const uint32_t aH = smem_u32(sAh), aL = smem_u32(sAl);
    const uint32_t bH = smem_u32(sBh);
    const int NC = K >> 4;

    float acc[2][6][4];
    #pragma unroll
    for (int i = 0; i < 2; i++)
        #pragma unroll
        for (int j = 0; j < 6; j++)
            #pragma unroll
            for (int q = 0; q < 4; q++) acc[i][j][q] = 0.f;

    const int lar = tid >> 1, lach = tid & 1;
    const int lbr = (tid < 192) ? (tid >> 1) : 0;
    const uint32_t aoffA = swz(lar, lach);
    const uint32_t aoffB = swz(lbr, lach);

    auto load_stage = [&](int c) {
        const int s = c & 3;
        const int k0 = c << 4;
        {
            uint32_t d = (uint32_t)(s * 4096) + aoffA;
            const size_t gs = (size_t)(bm + lar) * K + k0 + lach * 8;
            CPA16(aH + d, Ahi + gs);
            if (SPLITA) CPA16(aL + d, Alo + gs);
        }
        if (tid < 192) {
            uint32_t d = (uint32_t)(s * 3072) + aoffB;
            CPA16(bH + d, Bw + (size_t)(bn + lbr) * K + k0 + lach * 8);
        }
        CPA_COMMIT();
    };

    load_stage(0); load_stage(1); load_stage(2);

    const int arow0 = wm * 32 + (lane & 15);
    const int ach = lane >> 4;
    const int g = lane >> 3;
    const int brow0 = wn * 48 + ((g >> 1) << 3) + (lane & 7);
    const int bch = g & 1;

    for (int c = 0; c < NC; c++) {
        const int s = c & 3;
        CPA_WAIT2();
        __syncthreads();
        if (c + 3 < NC) load_stage(c + 3);
        else            CPA_COMMIT();

        uint32_t ah[2][4], al[2][4], bh[3][4];
        #pragma unroll
        for (int mt = 0; mt < 2; mt++) {
            int row = arow0 + mt * 16;
            uint32_t ad = (uint32_t)(s * 4096) + swz(row, ach);
            LDM4(ah[mt][0], ah[mt][1], ah[mt][2], ah[mt][3], aH + ad);
            if (SPLITA) LDM4(al[mt][0], al[mt][1], al[mt][2], al[mt][3], aL + ad);
        }
        #pragma unroll
        for (int p = 0; p < 3; p++) {
            int row = brow0 + p * 16;
            uint32_t bd = (uint32_t)(s * 3072) + swz(row, bch);
            LDM4(bh[p][0], bh[p][1], bh[p][2], bh[p][3], bH + bd);
        }
        #pragma unroll
        for (int mt = 0; mt < 2; mt++)
            #pragma unroll
            for (int p = 0; p < 3; p++)
                #pragma unroll
                for (int q = 0; q < 2; q++) {
                    float* d = acc[mt][p * 2 + q];
                    mma_f16(d, ah[mt], &bh[p][q * 2]);
                    if (SPLITA) mma_f16(d, al[mt], &bh[p][q * 2]);
                }
    }

    const float* biasp = bias + bn;
    #pragma unroll
    for (int mt = 0; mt < 2; mt++) {
        #pragma unroll
        for (int ro = 0; ro < 2; ro++) {
            int grow = bm + wm * 32 + mt * 16 + (lane >> 2) + ro * 8;
            size_t dstbase = (size_t)grow * Ntot;
            #pragma unroll
            for (int nt = 0; nt < 6; nt++) {
                int col = wn * 48 + nt * 8 + (lane & 3) * 2;
                float v0 = acc[mt][nt][ro * 2 + 0] + __ldg(biasp + col);
                float v1 = acc[mt][nt][ro * 2 + 1] + __ldg(biasp + col + 1);
                size_t oi = dstbase + bn + col;
                float2 rv = *(const float2*)&res[oi];
                float2 v; v.x = rv.x + v0; v.y = rv.y + v1;
                *(float2*)&outf[oi] = v;
            }
        }
    }
}

// ---------------- MMA flash attention: one block per (window, head), 4 warps ----------------
__global__ __launch_bounds__(128) void k_attn(const __half* __restrict__ qkvh,
                       const float* __restrict__ rpb_table,
                       __half* __restrict__ ohi, __half* __restrict__ olo) {
    __shared__ __align__(16) __half Qs[128 * 40];
    __shared__ __align__(16) __half Ks[128 * 40];
    __shared__ __align__(16) __half Vs[128 * 40];
    __shared__ float rpbh[736];
    __shared__ int   cjl[128];

    const int blk = blockIdx.x;
    const int win = blk / NH_, head = blk % NH_;
    const int tid = threadIdx.x;
    const int w = tid >> 5, lane = tid & 31;
    const __half* wbase = qkvh + (size_t)win * NTOK * C3 + head * HD_;

    {
        int r = tid >> 2, cc = (tid & 3) * 8;
        for (int rr = r; rr < 128; rr += 32) {
            const __half* p = wbase + (size_t)rr * C3;
            *(uint4*)&Qs[rr * 40 + cc] = *(const uint4*)(p + cc);
            *(uint4*)&Ks[rr * 40 + cc] = *(const uint4*)(p + 192 + cc);
            *(uint4*)&Vs[rr * 40 + cc] = *(const uint4*)(p + 384 + cc);
        }
    }
    for (int t = tid; t < 735; t += 128) rpbh[t] = rpb_table[t * NH_ + head];
    const int widx = win & 511;
    {
        int j = tid;
        int tj = j >> 4, hj = (j >> 2) & 3, wj = j & 3;
        int tb = widx >> 6, hb = (widx >> 3) & 7, wb = widx & 7;
        int gt = tb * 8 + tj, gh = hb * 4 + hj, gw = wb * 4 + wj;
        int rt = (gt < 56) ? 0 : (gt < 60 ? 1 : 2);
        int rh = (gh < 28) ? 0 : (gh < 30 ? 1 : 2);
        int rw = (gw < 28) ? 0 : (gw < 30 ? 1 : 2);
        cjl[j] = ((tj * 15 + hj * 7 + wj) << 5) | (rt * 9 + rh * 3 + rw);
    }
    __syncthreads();

    const bool uni = ((widx >> 6) < 7) && (((widx >> 3) & 7) < 7) && ((widx & 7) < 7);

    int ibase[4], ilab[4];
    #pragma unroll
    for (int rr = 0; rr < 4; rr++) {
        int i = w * 32 + (rr >> 1) * 16 + (rr & 1) * 8 + (lane >> 2);
        int v = cjl[i];
        ibase[rr] = (v >> 5) + 129;
        ilab[rr]  = v & 31;
    }

    uint32_t aq[2][2][4];
    #pragma unroll
    for (int kt = 0; kt < 2; kt++)
        #pragma unroll
        for (int mt = 0; mt < 2; mt++) {
            uint32_t ad = smem_u32(&Qs[(w * 32 + mt * 16 + (lane & 15)) * 40 + kt * 16 + 8 * (lane >> 4)]);
            LDM4(aq[kt][mt][0], aq[kt][mt][1], aq[kt][mt][2], aq[kt][mt][3], ad);
        }

    float m[4] = {-1e30f, -1e30f, -1e30f, -1e30f};
    float sum[4] = {};
    float acc2[2][4][4] = {};

    for (int kb = 0; kb < 4; kb++) {
        uint32_t bk[4][4];
        #pragma unroll
        for (int jn = 0; jn < 4; jn++) {
            uint32_t ad = smem_u32(&Ks[(kb * 32 + jn * 8 + (lane & 7)) * 40 + 8 * (lane >> 3)]);
            LDM4(bk[jn][0], bk[jn][1], bk[jn][2], bk[jn][3], ad);
        }
        float sc[2][4][4] = {};
        #pragma unroll
        for (int mt = 0; mt < 2; mt++)
            #pragma unroll
            for (int jn = 0; jn < 4; jn++) {
                mma_f16(sc[mt][jn], aq[0][mt], &bk[jn][0]);
                mma_f16(sc[mt][jn], aq[1][mt], &bk[jn][2]);
            }
        int jb = kb * 32 + (lane & 3) * 2;
        #pragma unroll
        for (int jn = 0; jn < 4; jn++) {
            int v0 = cjl[jb + jn * 8];
            int v1 = cjl[jb + jn * 8 + 1];
            #pragma unroll
            for (int mt = 0; mt < 2; mt++)
                #pragma unroll
                for (int c = 0; c < 4; c++) {
                    int vv = (c & 1) ? v1 : v0;
                    int rr = mt * 2 + (c >> 1);
                    float s = sc[mt][jn][c] * SCALE_ + rpbh[ibase[rr] - (vv >> 5)];
                    if (!uni && ilab[rr] != (vv & 31)) s -= 100.0f;
                    sc[mt][jn][c] = s;
                }
        }
        float rmax[4] = {-1e30f, -1e30f, -1e30f, -1e30f};
        #pragma unroll
        for (int mt = 0; mt < 2; mt++)
            #pragma unroll
            for (int jn = 0; jn < 4; jn++)
                #pragma unroll
                for (int c = 0; c < 4; c++)
                    rmax[mt * 2 + (c >> 1)] = fmaxf(rmax[mt * 2 + (c >> 1)], sc[mt][jn][c]);
        #pragma unroll
        for (int rr = 0; rr < 4; rr++) {
            rmax[rr] = fmaxf(rmax[rr], __shfl_xor_sync(0xffffffffu, rmax[rr], 1));
            rmax[rr] = fmaxf(rmax[rr], __shfl_xor_sync(0xffffffffu, rmax[rr], 2));
        }
        float corr[4];
        #pragma unroll
        for (int rr = 0; rr < 4; rr++) {
            float nm = fmaxf(m[rr], rmax[rr]);
            corr[rr] = __expf(m[rr] - nm);
            m[rr] = nm;
            sum[rr] *= corr[rr];
        }
        #pragma unroll
        for (int mt = 0; mt < 2; mt++)
            #pragma unroll
            for (int vn = 0; vn < 4; vn++)
                #pragma unroll
                for (int c = 0; c < 4; c++)
                    acc2[mt][vn][c] *= corr[mt * 2 + (c >> 1)];
        uint32_t ap[2][2][4];
        #pragma unroll
        for (int mt = 0; mt < 2; mt++)
            #pragma unroll
            for (int jn = 0; jn < 4; jn++) {
                float p0 = __expf(sc[mt][jn][0] - m[mt * 2]);
                float p1 = __expf(sc[mt][jn][1] - m[mt * 2]);
                float p2 = __expf(sc[mt][jn][2] - m[mt * 2 + 1]);
                float p3 = __expf(sc[mt][jn][3] - m[mt * 2 + 1]);
                sum[mt * 2]     += p0 + p1;
                sum[mt * 2 + 1] += p2 + p3;
                __half2 hA = __floats2half2_rn(p0, p1);
                __half2 hB = __floats2half2_rn(p2, p3);
                ap[jn >> 1][mt][(jn & 1) * 2]     = *(uint32_t*)&hA;
                ap[jn >> 1][mt][(jn & 1) * 2 + 1] = *(uint32_t*)&hB;
            }
        #pragma unroll
        for (int vn = 0; vn < 4; vn++) {
            uint32_t bv[4];
            uint32_t ad = smem_u32(&Vs[(kb * 32 + 8 * (lane >> 3) + (lane & 7)) * 40 + vn * 8]);
            LDM4T(bv[0], bv[1], bv[2], bv[3], ad);
            #pragma unroll
            for (int mt = 0; mt < 2; mt++) {
                mma_f16(acc2[mt][vn], ap[0][mt], &bv[0]);
                mma_f16(acc2[mt][vn], ap[1][mt], &bv[2]);
            }
        }
    }
    float inv[4];
    #pragma unroll
    for (int rr = 0; rr < 4; rr++) {
        sum[rr] += __shfl_xor_sync(0xffffffffu, sum[rr], 1);
        sum[rr] += __shfl_xor_sync(0xffffffffu, sum[rr], 2);
        inv[rr] = 1.0f / sum[rr];
    }
    #pragma unroll
    for (int mt = 0; mt < 2; mt++) {
        size_t row0 = (size_t)(win * 128 + w * 32 + mt * 16 + (lane >> 2));
        #pragma unroll
        for (int vn = 0; vn < 4; vn++) {
            size_t o = row0 * C_ + head * HD_ + vn * 8 + (lane & 3) * 2;
            float v0 = acc2[mt][vn][0] * inv[mt * 2];
            float v1 = acc2[mt][vn][1] * inv[mt * 2];
            __half h0, l0, h1, l1;
            split_f16(v0, h0, l0); split_f16(v1, h1, l1);
            *(__half2*)&ohi[o] = __halves2half2(h0, h1);
            *(__half2*)&olo[o] = __halves2half2(l0, l1);
            v0 = acc2[mt][vn][2] * inv[mt * 2 + 1];
            v1 = acc2[mt][vn][3] * inv[mt * 2 + 1];
            split_f16(v0, h0, l0); split_f16(v1, h1, l1);
            size_t o2 = o + 8 * C_;
            *(__half2*)&ohi[o2] = __halves2half2(h0, h1);
            *(__half2*)&olo[o2] = __halves2half2(l0, l1);
        }
    }
}

// ---------------- launch ----------------
#define ARES_SMEM 172032   // 48K + 48K + 2*36K

extern "C" void kernel_launch(void* const* d_in, const int* in_sizes, int n_in,
                              void* d_out, int out_size) {
    const float* x      = (const float*)d_in[0];
    const float* n1g    = (const float*)d_in[1];
    const float* n1b    = (const float*)d_in[2];
    const float* qkv_w  = (const float*)d_in[3];
    const float* qkv_b  = (const float*)d_in[4];
    const float* rpb    = (const float*)d_in[5];
    const float* proj_w = (const float*)d_in[6];
    const float* proj_b = (const float*)d_in[7];
    const float* n2g    = (const float*)d_in[8];
    const float* n2b    = (const float*)d_in[9];
    const float* fc1_w  = (const float*)d_in[10];
    const float* fc1_b  = (const float*)d_in[11];
    const float* fc2_w  = (const float*)d_in[12];
    const float* fc2_b  = (const float*)d_in[13];
    float* out = (float*)d_out;

    __half *acthi, *actlo, *hidhi, *w, *qkvh;
    float *x2;
    cudaGetSymbolAddress((void**)&acthi, g_act_hi);
    cudaGetSymbolAddress((void**)&actlo, g_act_lo);
    cudaGetSymbolAddress((void**)&hidhi, g_hid_hi);
    cudaGetSymbolAddress((void**)&w,     g_w);
    cudaGetSymbolAddress((void**)&qkvh,  g_qkvh);
    cudaGetSymbolAddress((void**)&x2,    g_x2);

    cudaFuncSetAttribute(k_gemm_ares<0, 6>, cudaFuncAttributeMaxDynamicSharedMemorySize, ARES_SMEM);
    cudaFuncSetAttribute(k_gemm_ares<1, 2>, cudaFuncAttributeMaxDynamicSharedMemorySize, ARES_SMEM);
    cudaFuncSetAttribute(k_gemm_ares<2, 8>, cudaFuncAttributeMaxDynamicSharedMemorySize, ARES_SMEM);

    const int OQKV = 0, OPROJ = 110592, OFC1 = 147456, OFC2 = 294912;

    k_wconv_all<<<(442368 + 255)/256, 256>>>(qkv_w, proj_w, fc1_w, fc2_w, w);

    // 1) LN1 + shift + partition -> act hi/lo (window rows, C)
    k_ln<true><<<ROWS, 192>>>(x, n1g, n1b, acthi, actlo);

    // 2) QKV GEMM (A-resident) -> g_qkvh fp16
    k_gemm_ares<0, 6><<<ROWS/128, 256, ARES_SMEM>>>(acthi, actlo, w + OQKV, qkv_b, nullptr, qkvh, nullptr);

    // 3) MMA windowed attention -> act hi/lo
    k_attn<<<BATCH * NWIN * NH_, 128>>>(qkvh, rpb, acthi, actlo);

    // 4) proj GEMM (A-resident) + reverse + roll + residual -> x2 fp32
    k_gemm_ares<1, 2><<<ROWS/128, 256, ARES_SMEM>>>(acthi, actlo, w + OPROJ, proj_b, x2, nullptr, x);

    // 5) LN2 -> act hi/lo
    k_ln<false><<<ROWS, 192>>>(x2, n2g, n2b, acthi, actlo);

    // 6) fc1 GEMM (A-resident) + GELU -> hidden fp16
    k_gemm_ares<2, 8><<<ROWS/128, 256, ARES_SMEM>>>(acthi, actlo, w + OFC1, fc1_b, nullptr, hidhi, nullptr);

    // 7) fc2 GEMM (4-stage pipelined, single-A) + residual -> d_out
    { dim3 g(C_/96, ROWS/128); k_mma_gemm<3, false><<<g, 256>>>(hidhi, nullptr, w + OFC2, fc2_b, 768, C_, out, nullptr, nullptr, x2); }
}

// round 15
// speedup vs baseline: 1.1906x; 1.1906x over previous
#include <cuda_runtime.h>
#include <cuda_fp16.h>
#include <math.h>
#include <stdint.h>

// ---------------- problem constants ----------------
#define BATCH 2
#define T_    64
#define H_    32
#define W_    32
#define C_    192
#define L_    (T_*H_*W_)
#define ROWS  (BATCH*L_)        // 131072 rows
#define NH_   6
#define HD_   32
#define NTOK  128
#define NWIN  512
#define C3    576
#define CM_   768
#define SCALE_ 0.17677669529663687f

// ---------------- scratch ----------------
__device__ __half g_act  [(size_t)ROWS * C_];
__device__ __half g_hid  [(size_t)ROWS * CM_];
__device__ __half g_qkvh [(size_t)ROWS * C3];
__device__ float  g_x2   [(size_t)ROWS * C_];
__device__ __half g_w    [442368];

// ---------------- helpers ----------------
__device__ __forceinline__ uint32_t smem_u32(const void* p) {
    uint32_t a;
    asm("{ .reg .u64 t; cvta.to.shared.u64 t, %1; cvt.u32.u64 %0, t; }" : "=r"(a) : "l"(p));
    return a;
}
#define CPA16(dst, src) asm volatile("cp.async.cg.shared.global [%0], [%1], 16;" :: "r"(dst), "l"(src))
#define CPA_COMMIT()    asm volatile("cp.async.commit_group;" ::: "memory")
#define CPA_WAIT0()     asm volatile("cp.async.wait_group 0;" ::: "memory")
#define CPA_WAIT2()     asm volatile("cp.async.wait_group 2;" ::: "memory")
#define LDM4(d0,d1,d2,d3,addr) \
    asm volatile("ldmatrix.sync.aligned.m8n8.x4.shared.b16 {%0,%1,%2,%3}, [%4];" \
        : "=r"(d0), "=r"(d1), "=r"(d2), "=r"(d3) : "r"(addr))
#define LDM4T(d0,d1,d2,d3,addr) \
    asm volatile("ldmatrix.sync.aligned.m8n8.x4.trans.shared.b16 {%0,%1,%2,%3}, [%4];" \
        : "=r"(d0), "=r"(d1), "=r"(d2), "=r"(d3) : "r"(addr))

__device__ __forceinline__ void mma_f16(float* c, const uint32_t* a, const uint32_t* b) {
    asm volatile("mma.sync.aligned.m16n8k16.row.col.f32.f16.f16.f32 "
        "{%0,%1,%2,%3},{%4,%5,%6,%7},{%8,%9},{%0,%1,%2,%3};"
        : "+f"(c[0]), "+f"(c[1]), "+f"(c[2]), "+f"(c[3])
        : "r"(a[0]), "r"(a[1]), "r"(a[2]), "r"(a[3]), "r"(b[0]), "r"(b[1]));
}

__device__ __forceinline__ size_t shifted_pos(int row) {
    int win = row >> 7, n = row & 127;
    int b  = win >> 9, widx = win & 511;
    int tb = widx >> 6, hb = (widx >> 3) & 7, wb = widx & 7;
    int ti = n >> 4,   hi = (n >> 2) & 3,    wi = n & 3;
    int t  = (tb*8 + ti + 4) & 63;
    int hh = (hb*4 + hi + 2) & 31;
    int ww = (wb*4 + wi + 2) & 31;
    return (size_t)b * L_ + (size_t)t * (H_*W_) + hh * W_ + ww;
}

// swizzled smem offset for a (row, 16B-chunk) pair, 32B logical rows, zero padding.
__device__ __forceinline__ uint32_t swz(int row, int ch) {
    return (uint32_t)(row * 32 + ((((row >> 2) & 1) ^ ch) << 4));
}

// ---------------- weight convert+transpose (all 4 weights) ----------------
__global__ void k_wconv_all(const float* __restrict__ qkv_w, const float* __restrict__ proj_w,
                            const float* __restrict__ fc1_w, const float* __restrict__ fc2_w,
                            __half* __restrict__ w) {
    int idx = blockIdx.x * 256 + threadIdx.x;
    if (idx >= 442368) return;
    const float* W; int K, N, off;
    if (idx < 110592)      { W = qkv_w;  K = 192; N = 576; off = 0; }
    else if (idx < 147456) { W = proj_w; K = 192; N = 192; off = 110592; }
    else if (idx < 294912) { W = fc1_w;  K = 192; N = 768; off = 147456; }
    else                   { W = fc2_w;  K = 768; N = 192; off = 294912; }
    int u = idx - off;
    int n = u / K, k = u - n * K;
    w[idx] = __float2half_rn(W[(size_t)k * N + n]);
}

// ---------------- layernorm -> fp16 ----------------
template<bool SHIFTMAP>
__global__ void k_ln(const float* __restrict__ x, const float* __restrict__ g,
                     const float* __restrict__ bt, __half* __restrict__ o) {
    int r = blockIdx.x;
    int c = threadIdx.x;
    size_t src = SHIFTMAP ? shifted_pos(r) * C_ : (size_t)r * C_;
    float v = x[src + c];
    float s1 = v, s2 = v * v;
    #pragma unroll
    for (int off = 16; off; off >>= 1) {
        s1 += __shfl_down_sync(0xffffffffu, s1, off);
        s2 += __shfl_down_sync(0xffffffffu, s2, off);
    }
    __shared__ float red[12];
    int warp = c >> 5, lane = c & 31;
    if (lane == 0) { red[warp] = s1; red[6 + warp] = s2; }
    __syncthreads();
    if (c == 0) {
        float a = 0.f, bb = 0.f;
        #pragma unroll
        for (int w2 = 0; w2 < 6; w2++) { a += red[w2]; bb += red[6 + w2]; }
        red[0] = a; red[6] = bb;
    }
    __syncthreads();
    float mu   = red[0] * (1.0f / 192.0f);
    float var  = red[6] * (1.0f / 192.0f) - mu * mu;
    float rstd = rsqrtf(var + 1e-5f);
    float y = (v - mu) * rstd * g[c] + bt[c];
    o[(size_t)r * C_ + c] = __float2half_rn(y);
}

// ---------------- A-resident GEMM (K=192, single fp16 A): CTA = 128 rows x ALL N ----------------
// smem: A [12 chunks x 128 x 32B] 48KB, B 2 x [12 chunks x 96 x 32B] 2x36KB = 120KB dynamic.
// MODE 0: oh = half(A*B + bias)                 (qkv, NT=6)
// MODE 1: outf[pos] = res[pos] + A*B + bias     (proj + reverse + roll + residual, NT=2)
// MODE 2: oh = half(gelu(A*B + bias))           (fc1, NT=8)
template<int MODE, int NT>
__global__ __launch_bounds__(256, 1) void k_gemm_ares(
    const __half* __restrict__ A,
    const __half* __restrict__ Bw, const float* __restrict__ bias,
    float* __restrict__ outf, __half* __restrict__ oh,
    const float* __restrict__ res)
{
    extern __shared__ __align__(16) uint8_t smem[];
    const int tid = threadIdx.x;
    const int bm = blockIdx.x * 128;
    const uint32_t aH = smem_u32(smem);
    const uint32_t bB = aH + 49152;

    // ---- stage A fully: 128 rows x 192 K ----
    #pragma unroll
    for (int i = 0; i < 12; i++) {
        int u = i * 256 + tid;          // 3072 (chunk, row, half16) slots
        int cch = u >> 8;
        int row = (u >> 1) & 127;
        int h = u & 1;
        CPA16(aH + (uint32_t)(cch * 4096) + swz(row, h),
              A + (size_t)(bm + row) * 192 + cch * 16 + h * 8);
    }
    CPA_COMMIT();

    auto load_B = [&](int nt, int s) {
        const __half* bp = Bw + (size_t)(nt * 96) * 192;
        uint32_t base = bB + (uint32_t)(s * 36864);
        #pragma unroll
        for (int i = 0; i < 9; i++) {
            int u = i * 256 + tid;      // 2304 slots
            int cch = u / 192;
            int v = u - cch * 192;
            int row = v >> 1, h = v & 1;
            CPA16(base + (uint32_t)(cch * 3072) + swz(row, h),
                  bp + (size_t)row * 192 + cch * 16 + h * 8);
        }
        CPA_COMMIT();
    };

    load_B(0, 0);
    CPA_WAIT0();
    __syncthreads();

    const int wid = tid >> 5, lane = tid & 31;
    const int wm = wid & 3, wn = wid >> 2;
    const int arow0 = wm * 32 + (lane & 15);
    const int ach = lane >> 4;
    const int g = lane >> 3;
    const int brow0 = wn * 48 + ((g >> 1) << 3) + (lane & 7);
    const int bch = g & 1;

    #pragma unroll 1
    for (int nt = 0; nt < NT; nt++) {
        const int s = nt & 1;
        if (nt + 1 < NT) load_B(nt + 1, s ^ 1);

        float acc[2][6][4] = {};
        const uint32_t bbase = bB + (uint32_t)(s * 36864);
        #pragma unroll
        for (int c = 0; c < 12; c++) {
            uint32_t ah[2][4], bh[3][4];
            #pragma unroll
            for (int mt = 0; mt < 2; mt++) {
                uint32_t ad = (uint32_t)(c * 4096) + swz(arow0 + mt * 16, ach);
                LDM4(ah[mt][0], ah[mt][1], ah[mt][2], ah[mt][3], aH + ad);
            }
            #pragma unroll
            for (int p = 0; p < 3; p++) {
                uint32_t bd = bbase + (uint32_t)(c * 3072) + swz(brow0 + p * 16, bch);
                LDM4(bh[p][0], bh[p][1], bh[p][2], bh[p][3], bd);
            }
            #pragma unroll
            for (int mt = 0; mt < 2; mt++)
                #pragma unroll
                for (int p = 0; p < 3; p++)
                    #pragma unroll
                    for (int q = 0; q < 2; q++)
                        mma_f16(acc[mt][p * 2 + q], ah[mt], &bh[p][q * 2]);
        }

        // ---- epilogue for columns [nt*96, nt*96+96) ----
        const int bn = nt * 96;
        const float* biasp = bias + bn;
        #pragma unroll
        for (int mt = 0; mt < 2; mt++) {
            #pragma unroll
            for (int ro = 0; ro < 2; ro++) {
                int grow = bm + wm * 32 + mt * 16 + (lane >> 2) + ro * 8;
                size_t dstbase;
                if (MODE == 1) dstbase = shifted_pos(grow) * (size_t)192;
                else           dstbase = (size_t)grow * (NT * 96);
                #pragma unroll
                for (int nc = 0; nc < 6; nc++) {
                    int col = wn * 48 + nc * 8 + (lane & 3) * 2;
                    float v0 = acc[mt][nc][ro * 2 + 0] + __ldg(biasp + col);
                    float v1 = acc[mt][nc][ro * 2 + 1] + __ldg(biasp + col + 1);
                    size_t oi = dstbase + bn + col;
                    if (MODE == 0) {
                        *(__half2*)&oh[oi] = __floats2half2_rn(v0, v1);
                    } else if (MODE == 2) {
                        v0 = 0.5f * v0 * (1.0f + erff(v0 * 0.70710678118654752f));
                        v1 = 0.5f * v1 * (1.0f + erff(v1 * 0.70710678118654752f));
                        *(__half2*)&oh[oi] = __floats2half2_rn(v0, v1);
                    } else {
                        float2 rv = *(const float2*)&res[oi];
                        float2 v; v.x = rv.x + v0; v.y = rv.y + v1;
                        *(float2*)&outf[oi] = v;
                    }
                }
            }
        }
        CPA_WAIT0();
        __syncthreads();
    }
}

// ---------------- 4-stage pipelined GEMM (fc2, K=768, single-A): outf = res + A*B + bias ----------------
__global__ __launch_bounds__(256, 2) void k_gemm_fc2(
    const __half* __restrict__ A, const __half* __restrict__ Bw,
    const float* __restrict__ bias, int K, int Ntot,
    float* __restrict__ outf, const float* __restrict__ res)
{
    __shared__ __align__(16) uint8_t sAh[4 * 128 * 32];
    __shared__ __align__(16) uint8_t sBh[4 * 96 * 32];

    const int tid = threadIdx.x;
    const int wid = tid >> 5, lane = tid & 31;
    const int wm = wid & 3, wn = wid >> 2;
    const int bm = blockIdx.y * 128;
    const int bn = blockIdx.x * 96;
    const uint32_t aH = smem_u32(sAh);
    const uint32_t bH = smem_u32(sBh);
    const int NC = K >> 4;

    float acc[2][6][4];
    #pragma unroll
    for (int i = 0; i < 2; i++)
        #pragma unroll
        for (int j = 0; j < 6; j++)
            #pragma unroll
            for (int q = 0; q < 4; q++) acc[i][j][q] = 0.f;

    const int lar = tid >> 1, lach = tid & 1;
    const int lbr = (tid < 192) ? (tid >> 1) : 0;
    const uint32_t aoffA = swz(lar, lach);
    const uint32_t aoffB = swz(lbr, lach);

    auto load_stage = [&](int c) {
        const int s = c & 3;
        const int k0 = c << 4;
        CPA16(aH + (uint32_t)(s * 4096) + aoffA, A + (size_t)(bm + lar) * K + k0 + lach * 8);
        if (tid < 192)
            CPA16(bH + (uint32_t)(s * 3072) + aoffB, Bw + (size_t)(bn + lbr) * K + k0 + lach * 8);
        CPA_COMMIT();
    };

    load_stage(0); load_stage(1); load_stage(2);

    const int arow0 = wm * 32 + (lane & 15);
    const int ach = lane >> 4;
    const int g = lane >> 3;
    const int brow0 = wn * 48 + ((g >> 1) << 3) + (lane & 7);
    const int bch = g & 1;

    for (int c = 0; c < NC; c++) {
        const int s = c & 3;
        CPA_WAIT2();
        __syncthreads();
        if (c + 3 < NC) load_stage(c + 3);
        else            CPA_COMMIT();

        uint32_t ah[2][4], bh[3][4];
        #pragma unroll
        for (int mt = 0; mt < 2; mt++) {
            uint32_t ad = (uint32_t)(s * 4096) + swz(arow0 + mt * 16, ach);
            LDM4(ah[mt][0], ah[mt][1], ah[mt][2], ah[mt][3], aH + ad);
        }
        #pragma unroll
        for (int p = 0; p < 3; p++) {
            uint32_t bd = (uint32_t)(s * 3072) + swz(brow0 + p * 16, bch);
            LDM4(bh[p][0], bh[p][1], bh[p][2], bh[p][3], bH + bd);
        }
        #pragma unroll
        for (int mt = 0; mt < 2; mt++)
            #pragma unroll
            for (int p = 0; p < 3; p++)
                #pragma unroll
                for (int q = 0; q < 2; q++)
                    mma_f16(acc[mt][p * 2 + q], ah[mt], &bh[p][q * 2]);
    }

    const float* biasp = bias + bn;
    #pragma unroll
    for (int mt = 0; mt < 2; mt++) {
        #pragma unroll
        for (int ro = 0; ro < 2; ro++) {
            int grow = bm + wm * 32 + mt * 16 + (lane >> 2) + ro * 8;
            size_t dstbase = (size_t)grow * Ntot;
            #pragma unroll
            for (int nt = 0; nt < 6; nt++) {
                int col = wn * 48 + nt * 8 + (lane & 3) * 2;
                float v0 = acc[mt][nt][ro * 2 + 0] + __ldg(biasp + col);
                float v1 = acc[mt][nt][ro * 2 + 1] + __ldg(biasp + col + 1);
                size_t oi = dstbase + bn + col;
                float2 rv = *(const float2*)&res[oi];
                float2 v; v.x = rv.x + v0; v.y = rv.y + v1;
                *(float2*)&outf[oi] = v;
            }
        }
    }
}

// ---------------- MMA flash attention: one block per (window, head), 4 warps ----------------
__global__ __launch_bounds__(128) void k_attn(const __half* __restrict__ qkvh,
                       const float* __restrict__ rpb_table,
                       __half* __restrict__ oh) {
    __shared__ __align__(16) __half Qs[128 * 40];
    __shared__ __align__(16) __half Ks[128 * 40];
    __shared__ __align__(16) __half Vs[128 * 40];
    __shared__ float rpbh[736];
    __shared__ int   cjl[128];

    const int blk = blockIdx.x;
    const int win = blk / NH_, head = blk % NH_;
    const int tid = threadIdx.x;
    const int w = tid >> 5, lane = tid & 31;
    const __half* wbase = qkvh + (size_t)win * NTOK * C3 + head * HD_;

    {
        int r = tid >> 2, cc = (tid & 3) * 8;
        for (int rr = r; rr < 128; rr += 32) {
            const __half* p = wbase + (size_t)rr * C3;
            *(uint4*)&Qs[rr * 40 + cc] = *(const uint4*)(p + cc);
            *(uint4*)&Ks[rr * 40 + cc] = *(const uint4*)(p + 192 + cc);
            *(uint4*)&Vs[rr * 40 + cc] = *(const uint4*)(p + 384 + cc);
        }
    }
    for (int t = tid; t < 735; t += 128) rpbh[t] = rpb_table[t * NH_ + head];
    const int widx = win & 511;
    {
        int j = tid;
        int tj = j >> 4, hj = (j >> 2) & 3, wj = j & 3;
        int tb = widx >> 6, hb = (widx >> 3) & 7, wb = widx & 7;
        int gt = tb * 8 + tj, gh = hb * 4 + hj, gw = wb * 4 + wj;
        int rt = (gt < 56) ? 0 : (gt < 60 ? 1 : 2);
        int rh = (gh < 28) ? 0 : (gh < 30 ? 1 : 2);
        int rw = (gw < 28) ? 0 : (gw < 30 ? 1 : 2);
        cjl[j] = ((tj * 15 + hj * 7 + wj) << 5) | (rt * 9 + rh * 3 + rw);
    }
    __syncthreads();

    const bool uni = ((widx >> 6) < 7) && (((widx >> 3) & 7) < 7) && ((widx & 7) < 7);

    int ibase[4], ilab[4];
    #pragma unroll
    for (int rr = 0; rr < 4; rr++) {
        int i = w * 32 + (rr >> 1) * 16 + (rr & 1) * 8 + (lane >> 2);
        int v = cjl[i];
        ibase[rr] = (v >> 5) + 129;
        ilab[rr]  = v & 31;
    }

    uint32_t aq[2][2][4];
    #pragma unroll
    for (int kt = 0; kt < 2; kt++)
        #pragma unroll
        for (int mt = 0; mt < 2; mt++) {
            uint32_t ad = smem_u32(&Qs[(w * 32 + mt * 16 + (lane & 15)) * 40 + kt * 16 + 8 * (lane >> 4)]);
            LDM4(aq[kt][mt][0], aq[kt][mt][1], aq[kt][mt][2], aq[kt][mt][3], ad);
        }

    float m[4] = {-1e30f, -1e30f, -1e30f, -1e30f};
    float sum[4] = {};
    float acc2[2][4][4] = {};

    for (int kb = 0; kb < 4; kb++) {
        uint32_t bk[4][4];
        #pragma unroll
        for (int jn = 0; jn < 4; jn++) {
            uint32_t ad = smem_u32(&Ks[(kb * 32 + jn * 8 + (lane & 7)) * 40 + 8 * (lane >> 3)]);
            LDM4(bk[jn][0], bk[jn][1], bk[jn][2], bk[jn][3], ad);
        }
        float sc[2][4][4] = {};
        #pragma unroll
        for (int mt = 0; mt < 2; mt++)
            #pragma unroll
            for (int jn = 0; jn < 4; jn++) {
                mma_f16(sc[mt][jn], aq[0][mt], &bk[jn][0]);
                mma_f16(sc[mt][jn], aq[1][mt], &bk[jn][2]);
            }
        int jb = kb * 32 + (lane & 3) * 2;
        #pragma unroll
        for (int jn = 0; jn < 4; jn++) {
            int v0 = cjl[jb + jn * 8];
            int v1 = cjl[jb + jn * 8 + 1];
            #pragma unroll
            for (int mt = 0; mt < 2; mt++)
                #pragma unroll
                for (int c = 0; c < 4; c++) {
                    int vv = (c & 1) ? v1 : v0;
                    int rr = mt * 2 + (c >> 1);
                    float s = sc[mt][jn][c] * SCALE_ + rpbh[ibase[rr] - (vv >> 5)];
                    if (!uni && ilab[rr] != (vv & 31)) s -= 100.0f;
                    sc[mt][jn][c] = s;
                }
        }
        float rmax[4] = {-1e30f, -1e30f, -1e30f, -1e30f};
        #pragma unroll
        for (int mt = 0; mt < 2; mt++)
            #pragma unroll
            for (int jn = 0; jn < 4; jn++)
                #pragma unroll
                for (int c = 0; c < 4; c++)
                    rmax[mt * 2 + (c >> 1)] = fmaxf(rmax[mt * 2 + (c >> 1)], sc[mt][jn][c]);
        #pragma unroll
        for (int rr = 0; rr < 4; rr++) {
            rmax[rr] = fmaxf(rmax[rr], __shfl_xor_sync(0xffffffffu, rmax[rr], 1));
            rmax[rr] = fmaxf(rmax[rr], __shfl_xor_sync(0xffffffffu, rmax[rr], 2));
        }
        float corr[4];
        #pragma unroll
        for (int rr = 0; rr < 4; rr++) {
            float nm = fmaxf(m[rr], rmax[rr]);
            corr[rr] = __expf(m[rr] - nm);
            m[rr] = nm;
            sum[rr] *= corr[rr];
        }
        #pragma unroll
        for (int mt = 0; mt < 2; mt++)
            #pragma unroll
            for (int vn = 0; vn < 4; vn++)
                #pragma unroll
                for (int c = 0; c < 4; c++)
                    acc2[mt][vn][c] *= corr[mt * 2 + (c >> 1)];
        uint32_t ap[2][2][4];
        #pragma unroll
        for (int mt = 0; mt < 2; mt++)
            #pragma unroll
            for (int jn = 0; jn < 4; jn++) {
                float p0 = __expf(sc[mt][jn][0] - m[mt * 2]);
                float p1 = __expf(sc[mt][jn][1] - m[mt * 2]);
                float p2 = __expf(sc[mt][jn][2] - m[mt * 2 + 1]);
                float p3 = __expf(sc[mt][jn][3] - m[mt * 2 + 1]);
                sum[mt * 2]     += p0 + p1;
                sum[mt * 2 + 1] += p2 + p3;
                __half2 hA = __floats2half2_rn(p0, p1);
                __half2 hB = __floats2half2_rn(p2, p3);
                ap[jn >> 1][mt][(jn & 1) * 2]     = *(uint32_t*)&hA;
                ap[jn >> 1][mt][(jn & 1) * 2 + 1] = *(uint32_t*)&hB;
            }
        #pragma unroll
        for (int vn = 0; vn < 4; vn++) {
            uint32_t bv[4];
            uint32_t ad = smem_u32(&Vs[(kb * 32 + 8 * (lane >> 3) + (lane & 7)) * 40 + vn * 8]);
            LDM4T(bv[0], bv[1], bv[2], bv[3], ad);
            #pragma unroll
            for (int mt = 0; mt < 2; mt++) {
                mma_f16(acc2[mt][vn], ap[0][mt], &bv[0]);
                mma_f16(acc2[mt][vn], ap[1][mt], &bv[2]);
            }
        }
    }
    float inv[4];
    #pragma unroll
    for (int rr = 0; rr < 4; rr++) {
        sum[rr] += __shfl_xor_sync(0xffffffffu, sum[rr], 1);
        sum[rr] += __shfl_xor_sync(0xffffffffu, sum[rr], 2);
        inv[rr] = 1.0f / sum[rr];
    }
    #pragma unroll
    for (int mt = 0; mt < 2; mt++) {
        size_t row0 = (size_t)(win * 128 + w * 32 + mt * 16 + (lane >> 2));
        #pragma unroll
        for (int vn = 0; vn < 4; vn++) {
            size_t o = row0 * C_ + head * HD_ + vn * 8 + (lane & 3) * 2;
            *(__half2*)&oh[o] = __floats2half2_rn(acc2[mt][vn][0] * inv[mt * 2],
                                                  acc2[mt][vn][1] * inv[mt * 2]);
            size_t o2 = o + 8 * C_;
            *(__half2*)&oh[o2] = __floats2half2_rn(acc2[mt][vn][2] * inv[mt * 2 + 1],
                                                   acc2[mt][vn][3] * inv[mt * 2 + 1]);
        }
    }
}

// ---------------- launch ----------------
#define ARES_SMEM 122880   // 48K (A) + 2*36K (B)

extern "C" void kernel_launch(void* const* d_in, const int* in_sizes, int n_in,
                              void* d_out, int out_size) {
    const float* x      = (const float*)d_in[0];
    const float* n1g    = (const float*)d_in[1];
    const float* n1b    = (const float*)d_in[2];
    const float* qkv_w  = (const float*)d_in[3];
    const float* qkv_b  = (const float*)d_in[4];
    const float* rpb    = (const float*)d_in[5];
    const float* proj_w = (const float*)d_in[6];
    const float* proj_b = (const float*)d_in[7];
    const float* n2g    = (const float*)d_in[8];
    const float* n2b    = (const float*)d_in[9];
    const float* fc1_w  = (const float*)d_in[10];
    const float* fc1_b  = (const float*)d_in[11];
    const float* fc2_w  = (const float*)d_in[12];
    const float* fc2_b  = (const float*)d_in[13];
    float* out = (float*)d_out;

    __half *act, *hid, *w, *qkvh;
    float *x2;
    cudaGetSymbolAddress((void**)&act,  g_act);
    cudaGetSymbolAddress((void**)&hid,  g_hid);
    cudaGetSymbolAddress((void**)&w,    g_w);
    cudaGetSymbolAddress((void**)&qkvh, g_qkvh);
    cudaGetSymbolAddress((void**)&x2,   g_x2);

    cudaFuncSetAttribute(k_gemm_ares<0, 6>, cudaFuncAttributeMaxDynamicSharedMemorySize, ARES_SMEM);
    cudaFuncSetAttribute(k_gemm_ares<1, 2>, cudaFuncAttributeMaxDynamicSharedMemorySize, ARES_SMEM);
    cudaFuncSetAttribute(k_gemm_ares<2, 8>, cudaFuncAttributeMaxDynamicSharedMemorySize, ARES_SMEM);

    const int OQKV = 0, OPROJ = 110592, OFC1 = 147456, OFC2 = 294912;

    k_wconv_all<<<(442368 + 255)/256, 256>>>(qkv_w, proj_w, fc1_w, fc2_w, w);

    // 1) LN1 + shift + partition -> act fp16 (window rows, C)
    k_ln<true><<<ROWS, 192>>>(x, n1g, n1b, act);

    // 2) QKV GEMM (A-resident) -> g_qkvh fp16
    k_gemm_ares<0, 6><<<ROWS/128, 256, ARES_SMEM>>>(act, w + OQKV, qkv_b, nullptr, qkvh, nullptr);

    // 3) MMA windowed attention -> act fp16
    k_attn<<<BATCH * NWIN * NH_, 128>>>(qkvh, rpb, act);

    // 4) proj GEMM (A-resident) + reverse + roll + residual -> x2 fp32
    k_gemm_ares<1, 2><<<ROWS/128, 256, ARES_SMEM>>>(act, w + OPROJ, proj_b, x2, nullptr, x);

    // 5) LN2 -> act fp16
    k_ln<false><<<ROWS, 192>>>(x2, n2g, n2b, act);

    // 6) fc1 GEMM (A-resident) + GELU -> hid fp16
    k_gemm_ares<2, 8><<<ROWS/128, 256, ARES_SMEM>>>(act, w + OFC1, fc1_b, nullptr, hid, nullptr);

    // 7) fc2 GEMM (4-stage pipelined) + residual -> d_out
    { dim3 g(C_/96, ROWS/128); k_gemm_fc2<<<g, 256>>>(hid, w + OFC2, fc2_b, 768, C_, out, x2); }
}

// round 16
// speedup vs baseline: 1.3855x; 1.1637x over previous
#include <cuda_runtime.h>
#include <cuda_fp16.h>
#include <math.h>
#include <stdint.h>

// ---------------- problem constants ----------------
#define BATCH 2
#define T_    64
#define H_    32
#define W_    32
#define C_    192
#define L_    (T_*H_*W_)
#define ROWS  (BATCH*L_)        // 131072 rows
#define NH_   6
#define HD_   32
#define NTOK  128
#define NWIN  512
#define C3    576
#define CM_   768
#define SCALE_ 0.17677669529663687f

// ---------------- scratch ----------------
__device__ __half g_act  [(size_t)ROWS * C_];
__device__ __half g_hid  [(size_t)ROWS * CM_];
__device__ __half g_qkvh [(size_t)ROWS * C3];
__device__ float  g_x2   [(size_t)ROWS * C_];
__device__ __half g_w    [442368];

// ---------------- helpers ----------------
__device__ __forceinline__ uint32_t smem_u32(const void* p) {
    uint32_t a;
    asm("{ .reg .u64 t; cvta.to.shared.u64 t, %1; cvt.u32.u64 %0, t; }" : "=r"(a) : "l"(p));
    return a;
}
#define CPA16(dst, src) asm volatile("cp.async.cg.shared.global [%0], [%1], 16;" :: "r"(dst), "l"(src))
#define CPA_COMMIT()    asm volatile("cp.async.commit_group;" ::: "memory")
#define CPA_WAIT0()     asm volatile("cp.async.wait_group 0;" ::: "memory")
#define CPA_WAIT2()     asm volatile("cp.async.wait_group 2;" ::: "memory")
#define LDM4(d0,d1,d2,d3,addr) \
    asm volatile("ldmatrix.sync.aligned.m8n8.x4.shared.b16 {%0,%1,%2,%3}, [%4];" \
        : "=r"(d0), "=r"(d1), "=r"(d2), "=r"(d3) : "r"(addr))
#define LDM4T(d0,d1,d2,d3,addr) \
    asm volatile("ldmatrix.sync.aligned.m8n8.x4.trans.shared.b16 {%0,%1,%2,%3}, [%4];" \
        : "=r"(d0), "=r"(d1), "=r"(d2), "=r"(d3) : "r"(addr))

__device__ __forceinline__ void mma_f16(float* c, const uint32_t* a, const uint32_t* b) {
    asm volatile("mma.sync.aligned.m16n8k16.row.col.f32.f16.f16.f32 "
        "{%0,%1,%2,%3},{%4,%5,%6,%7},{%8,%9},{%0,%1,%2,%3};"
        : "+f"(c[0]), "+f"(c[1]), "+f"(c[2]), "+f"(c[3])
        : "r"(a[0]), "r"(a[1]), "r"(a[2]), "r"(a[3]), "r"(b[0]), "r"(b[1]));
}

__device__ __forceinline__ size_t shifted_pos(int row) {
    int win = row >> 7, n = row & 127;
    int b  = win >> 9, widx = win & 511;
    int tb = widx >> 6, hb = (widx >> 3) & 7, wb = widx & 7;
    int ti = n >> 4,   hi = (n >> 2) & 3,    wi = n & 3;
    int t  = (tb*8 + ti + 4) & 63;
    int hh = (hb*4 + hi + 2) & 31;
    int ww = (wb*4 + wi + 2) & 31;
    return (size_t)b * L_ + (size_t)t * (H_*W_) + hh * W_ + ww;
}

// swizzled smem offset for a (row, 16B-chunk) pair, 32B logical rows, zero padding.
__device__ __forceinline__ uint32_t swz(int row, int ch) {
    return (uint32_t)(row * 32 + ((((row >> 2) & 1) ^ ch) << 4));
}

// ---------------- weight convert+transpose (all 4 weights) ----------------
__global__ void k_wconv_all(const float* __restrict__ qkv_w, const float* __restrict__ proj_w,
                            const float* __restrict__ fc1_w, const float* __restrict__ fc2_w,
                            __half* __restrict__ w) {
    int idx = blockIdx.x * 256 + threadIdx.x;
    if (idx >= 442368) return;
    const float* W; int K, N, off;
    if (idx < 110592)      { W = qkv_w;  K = 192; N = 576; off = 0; }
    else if (idx < 147456) { W = proj_w; K = 192; N = 192; off = 110592; }
    else if (idx < 294912) { W = fc1_w;  K = 192; N = 768; off = 147456; }
    else                   { W = fc2_w;  K = 768; N = 192; off = 294912; }
    int u = idx - off;
    int n = u / K, k = u - n * K;
    w[idx] = __float2half_rn(W[(size_t)k * N + n]);
}

// ---------------- A-resident GEMM (K=192), optional fused LN in A-staging ----------------
// smem: A [12 chunks x 128 x 32B] 48KB, B 2 x 36KB, gamma/beta 1.5KB = 124416 dynamic.
// MODE 0 (LNSTAGE, gathered):  oh = half(LN(x)*B + bias)          (qkv, NT=6)
// MODE 1:                      outf[pos] = res[pos] + A*B + bias  (proj+reverse+roll+residual, NT=2)
// MODE 2 (LNSTAGE, natural):   oh = half(gelu(LN(x2)*B + bias))   (fc1, NT=8)
template<int MODE, int NT, bool LNSTAGE>
__global__ __launch_bounds__(256, 1) void k_gemm_ares(
    const __half* __restrict__ A, const float* __restrict__ Xf,
    const float* __restrict__ gvec, const float* __restrict__ bvec,
    const __half* __restrict__ Bw, const float* __restrict__ bias,
    float* __restrict__ outf, __half* __restrict__ oh,
    const float* __restrict__ res)
{
    extern __shared__ __align__(16) uint8_t smem[];
    const int tid = threadIdx.x;
    const int bm = blockIdx.x * 128;
    const uint32_t aH = smem_u32(smem);
    const uint32_t bB = aH + 49152;
    float* sg = (float*)(smem + 122880);
    float* sb = sg + 192;

    auto load_B = [&](int nt, int s) {
        const __half* bp = Bw + (size_t)(nt * 96) * 192;
        uint32_t base = bB + (uint32_t)(s * 36864);
        #pragma unroll
        for (int i = 0; i < 9; i++) {
            int u = i * 256 + tid;      // 2304 slots
            int cch = u / 192;
            int v = u - cch * 192;
            int row = v >> 1, h = v & 1;
            CPA16(base + (uint32_t)(cch * 3072) + swz(row, h),
                  bp + (size_t)row * 192 + cch * 16 + h * 8);
        }
        CPA_COMMIT();
    };

    // kick off B0 first so it overlaps A staging
    load_B(0, 0);

    if (LNSTAGE) {
        // fused layernorm staging: 2 threads per row, two-pass
        if (tid < 192) { sg[tid] = gvec[tid]; sb[tid] = bvec[tid]; }
        int row = tid >> 1, hh = tid & 1;
        size_t srow = (MODE == 0) ? shifted_pos(bm + row) : (size_t)(bm + row);
        const float4* xr = (const float4*)(Xf + srow * 192 + hh * 96);
        float s1 = 0.f, s2 = 0.f;
        #pragma unroll
        for (int i = 0; i < 24; i++) {
            float4 t = __ldg(xr + i);
            s1 += t.x + t.y + t.z + t.w;
            s2 += t.x*t.x + t.y*t.y + t.z*t.z + t.w*t.w;
        }
        s1 += __shfl_xor_sync(0xffffffffu, s1, 1);
        s2 += __shfl_xor_sync(0xffffffffu, s2, 1);
        float mu   = s1 * (1.0f / 192.0f);
        float var  = s2 * (1.0f / 192.0f) - mu * mu;
        float rstd = rsqrtf(var + 1e-5f);
        __syncthreads();   // sg/sb visible
        #pragma unroll
        for (int c16 = 0; c16 < 6; c16++) {
            int cch = hh * 6 + c16;
            #pragma unroll
            for (int h = 0; h < 2; h++) {
                float4 a = __ldg(xr + c16 * 4 + h * 2);
                float4 b = __ldg(xr + c16 * 4 + h * 2 + 1);
                int cb = hh * 96 + c16 * 16 + h * 8;
                __half2 o0 = __floats2half2_rn((a.x - mu) * rstd * sg[cb+0] + sb[cb+0],
                                               (a.y - mu) * rstd * sg[cb+1] + sb[cb+1]);
                __half2 o1 = __floats2half2_rn((a.z - mu) * rstd * sg[cb+2] + sb[cb+2],
                                               (a.w - mu) * rstd * sg[cb+3] + sb[cb+3]);
                __half2 o2 = __floats2half2_rn((b.x - mu) * rstd * sg[cb+4] + sb[cb+4],
                                               (b.y - mu) * rstd * sg[cb+5] + sb[cb+5]);
                __half2 o3 = __floats2half2_rn((b.z - mu) * rstd * sg[cb+6] + sb[cb+6],
                                               (b.w - mu) * rstd * sg[cb+7] + sb[cb+7]);
                uint4 st;
                st.x = *(uint32_t*)&o0; st.y = *(uint32_t*)&o1;
                st.z = *(uint32_t*)&o2; st.w = *(uint32_t*)&o3;
                *(uint4*)(smem + cch * 4096 + swz(row, h)) = st;
            }
        }
    } else {
        // plain fp16 A staging via cp.async
        #pragma unroll
        for (int i = 0; i < 12; i++) {
            int u = i * 256 + tid;
            int cch = u >> 8;
            int row = (u >> 1) & 127;
            int h = u & 1;
            CPA16(aH + (uint32_t)(cch * 4096) + swz(row, h),
                  A + (size_t)(bm + row) * 192 + cch * 16 + h * 8);
        }
        CPA_COMMIT();
    }

    CPA_WAIT0();
    __syncthreads();

    const int wid = tid >> 5, lane = tid & 31;
    const int wm = wid & 3, wn = wid >> 2;
    const int arow0 = wm * 32 + (lane & 15);
    const int ach = lane >> 4;
    const int g = lane >> 3;
    const int brow0 = wn * 48 + ((g >> 1) << 3) + (lane & 7);
    const int bch = g & 1;

    #pragma unroll 1
    for (int nt = 0; nt < NT; nt++) {
        const int s = nt & 1;
        if (nt + 1 < NT) load_B(nt + 1, s ^ 1);

        float acc[2][6][4] = {};
        const uint32_t bbase = bB + (uint32_t)(s * 36864);
        #pragma unroll
        for (int c = 0; c < 12; c++) {
            uint32_t ah[2][4], bh[3][4];
            #pragma unroll
            for (int mt = 0; mt < 2; mt++) {
                uint32_t ad = (uint32_t)(c * 4096) + swz(arow0 + mt * 16, ach);
                LDM4(ah[mt][0], ah[mt][1], ah[mt][2], ah[mt][3], aH + ad);
            }
            #pragma unroll
            for (int p = 0; p < 3; p++) {
                uint32_t bd = bbase + (uint32_t)(c * 3072) + swz(brow0 + p * 16, bch);
                LDM4(bh[p][0], bh[p][1], bh[p][2], bh[p][3], bd);
            }
            #pragma unroll
            for (int mt = 0; mt < 2; mt++)
                #pragma unroll
                for (int p = 0; p < 3; p++)
                    #pragma unroll
                    for (int q = 0; q < 2; q++)
                        mma_f16(acc[mt][p * 2 + q], ah[mt], &bh[p][q * 2]);
        }

        // ---- epilogue for columns [nt*96, nt*96+96) ----
        const int bn = nt * 96;
        const float* biasp = bias + bn;
        #pragma unroll
        for (int mt = 0; mt < 2; mt++) {
            #pragma unroll
            for (int ro = 0; ro < 2; ro++) {
                int grow = bm + wm * 32 + mt * 16 + (lane >> 2) + ro * 8;
                size_t dstbase;
                if (MODE == 1) dstbase = shifted_pos(grow) * (size_t)192;
                else           dstbase = (size_t)grow * (NT * 96);
                #pragma unroll
                for (int nc = 0; nc < 6; nc++) {
                    int col = wn * 48 + nc * 8 + (lane & 3) * 2;
                    float v0 = acc[mt][nc][ro * 2 + 0] + __ldg(biasp + col);
                    float v1 = acc[mt][nc][ro * 2 + 1] + __ldg(biasp + col + 1);
                    size_t oi = dstbase + bn + col;
                    if (MODE == 0) {
                        *(__half2*)&oh[oi] = __floats2half2_rn(v0, v1);
                    } else if (MODE == 2) {
                        v0 = 0.5f * v0 * (1.0f + erff(v0 * 0.70710678118654752f));
                        v1 = 0.5f * v1 * (1.0f + erff(v1 * 0.70710678118654752f));
                        *(__half2*)&oh[oi] = __floats2half2_rn(v0, v1);
                    } else {
                        float2 rv = *(const float2*)&res[oi];
                        float2 v; v.x = rv.x + v0; v.y = rv.y + v1;
                        *(float2*)&outf[oi] = v;
                    }
                }
            }
        }
        CPA_WAIT0();
        __syncthreads();
    }
}

// ---------------- 4-stage pipelined GEMM (fc2, K=768, single-A): outf = res + A*B + bias ----------------
__global__ __launch_bounds__(256, 2) void k_gemm_fc2(
    const __half* __restrict__ A, const __half* __restrict__ Bw,
    const float* __restrict__ bias, int K, int Ntot,
    float* __restrict__ outf, const float* __restrict__ res)
{
    __shared__ __align__(16) uint8_t sAh[4 * 128 * 32];
    __shared__ __align__(16) uint8_t sBh[4 * 96 * 32];

    const int tid = threadIdx.x;
    const int wid = tid >> 5, lane = tid & 31;
    const int wm = wid & 3, wn = wid >> 2;
    const int bm = blockIdx.y * 128;
    const int bn = blockIdx.x * 96;
    const uint32_t aH = smem_u32(sAh);
    const uint32_t bH = smem_u32(sBh);
    const int NC = K >> 4;

    float acc[2][6][4];
    #pragma unroll
    for (int i = 0; i < 2; i++)
        #pragma unroll
        for (int j = 0; j < 6; j++)
            #pragma unroll
            for (int q = 0; q < 4; q++) acc[i][j][q] = 0.f;

    const int lar = tid >> 1, lach = tid & 1;
    const int lbr = (tid < 192) ? (tid >> 1) : 0;
    const uint32_t aoffA = swz(lar, lach);
    const uint32_t aoffB = swz(lbr, lach);

    auto load_stage = [&](int c) {
        const int s = c & 3;
        const int k0 = c << 4;
        CPA16(aH + (uint32_t)(s * 4096) + aoffA, A + (size_t)(bm + lar) * K + k0 + lach * 8);
        if (tid < 192)
            CPA16(bH + (uint32_t)(s * 3072) + aoffB, Bw + (size_t)(bn + lbr) * K + k0 + lach * 8);
        CPA_COMMIT();
    };

    load_stage(0); load_stage(1); load_stage(2);

    const int arow0 = wm * 32 + (lane & 15);
    const int ach = lane >> 4;
    const int g = lane >> 3;
    const int brow0 = wn * 48 + ((g >> 1) << 3) + (lane & 7);
    const int bch = g & 1;

    for (int c = 0; c < NC; c++) {
        const int s = c & 3;
        CPA_WAIT2();
        __syncthreads();
        if (c + 3 < NC) load_stage(c + 3);
        else            CPA_COMMIT();

        uint32_t ah[2][4], bh[3][4];
        #pragma unroll
        for (int mt = 0; mt < 2; mt++) {
            uint32_t ad = (uint32_t)(s * 4096) + swz(arow0 + mt * 16, ach);
            LDM4(ah[mt][0], ah[mt][1], ah[mt][2], ah[mt][3], aH + ad);
        }
        #pragma unroll
        for (int p = 0; p < 3; p++) {
            uint32_t bd = (uint32_t)(s * 3072) + swz(brow0 + p * 16, bch);
            LDM4(bh[p][0], bh[p][1], bh[p][2], bh[p][3], bH + bd);
        }
        #pragma unroll
        for (int mt = 0; mt < 2; mt++)
            #pragma unroll
            for (int p = 0; p < 3; p++)
                #pragma unroll
                for (int q = 0; q < 2; q++)
                    mma_f16(acc[mt][p * 2 + q], ah[mt], &bh[p][q * 2]);
    }

    const float* biasp = bias + bn;
    #pragma unroll
    for (int mt = 0; mt < 2; mt++) {
        #pragma unroll
        for (int ro = 0; ro < 2; ro++) {
            int grow = bm + wm * 32 + mt * 16 + (lane >> 2) + ro * 8;
            size_t dstbase = (size_t)grow * Ntot;
            #pragma unroll
            for (int nt = 0; nt < 6; nt++) {
                int col = wn * 48 + nt * 8 + (lane & 3) * 2;
                float v0 = acc[mt][nt][ro * 2 + 0] + __ldg(biasp + col);
                float v1 = acc[mt][nt][ro * 2 + 1] + __ldg(biasp + col + 1);
                size_t oi = dstbase + bn + col;
                float2 rv = *(const float2*)&res[oi];
                float2 v; v.x = rv.x + v0; v.y = rv.y + v1;
                *(float2*)&outf[oi] = v;
            }
        }
    }
}

// ---------------- MMA flash attention: one block per (window, head), 4 warps ----------------
__global__ __launch_bounds__(128) void k_attn(const __half* __restrict__ qkvh,
                       const float* __restrict__ rpb_table,
                       __half* __restrict__ oh) {
    __shared__ __align__(16) __half Qs[128 * 40];
    __shared__ __align__(16) __half Ks[128 * 40];
    __shared__ __align__(16) __half Vs[128 * 40];
    __shared__ float rpbh[736];
    __shared__ int   cjl[128];

    const int blk = blockIdx.x;
    const int win = blk / NH_, head = blk % NH_;
    const int tid = threadIdx.x;
    const int w = tid >> 5, lane = tid & 31;
    const __half* wbase = qkvh + (size_t)win * NTOK * C3 + head * HD_;

    {
        int r = tid >> 2, cc = (tid & 3) * 8;
        for (int rr = r; rr < 128; rr += 32) {
            const __half* p = wbase + (size_t)rr * C3;
            *(uint4*)&Qs[rr * 40 + cc] = *(const uint4*)(p + cc);
            *(uint4*)&Ks[rr * 40 + cc] = *(const uint4*)(p + 192 + cc);
            *(uint4*)&Vs[rr * 40 + cc] = *(const uint4*)(p + 384 + cc);
        }
    }
    for (int t = tid; t < 735; t += 128) rpbh[t] = rpb_table[t * NH_ + head];
    const int widx = win & 511;
    {
        int j = tid;
        int tj = j >> 4, hj = (j >> 2) & 3, wj = j & 3;
        int tb = widx >> 6, hb = (widx >> 3) & 7, wb = widx & 7;
        int gt = tb * 8 + tj, gh = hb * 4 + hj, gw = wb * 4 + wj;
        int rt = (gt < 56) ? 0 : (gt < 60 ? 1 : 2);
        int rh = (gh < 28) ? 0 : (gh < 30 ? 1 : 2);
        int rw = (gw < 28) ? 0 : (gw < 30 ? 1 : 2);
        cjl[j] = ((tj * 15 + hj * 7 + wj) << 5) | (rt * 9 + rh * 3 + rw);
    }
    __syncthreads();

    const bool uni = ((widx >> 6) < 7) && (((widx >> 3) & 7) < 7) && ((widx & 7) < 7);

    int ibase[4], ilab[4];
    #pragma unroll
    for (int rr = 0; rr < 4; rr++) {
        int i = w * 32 + (rr >> 1) * 16 + (rr & 1) * 8 + (lane >> 2);
        int v = cjl[i];
        ibase[rr] = (v >> 5) + 129;
        ilab[rr]  = v & 31;
    }

    uint32_t aq[2][2][4];
    #pragma unroll
    for (int kt = 0; kt < 2; kt++)
        #pragma unroll
        for (int mt = 0; mt < 2; mt++) {
            uint32_t ad = smem_u32(&Qs[(w * 32 + mt * 16 + (lane & 15)) * 40 + kt * 16 + 8 * (lane >> 4)]);
            LDM4(aq[kt][mt][0], aq[kt][mt][1], aq[kt][mt][2], aq[kt][mt][3], ad);
        }

    float m[4] = {-1e30f, -1e30f, -1e30f, -1e30f};
    float sum[4] = {};
    float acc2[2][4][4] = {};

    for (int kb = 0; kb < 4; kb++) {
        uint32_t bk[4][4];
        #pragma unroll
        for (int jn = 0; jn < 4; jn++) {
            uint32_t ad = smem_u32(&Ks[(kb * 32 + jn * 8 + (lane & 7)) * 40 + 8 * (lane >> 3)]);
            LDM4(bk[jn][0], bk[jn][1], bk[jn][2], bk[jn][3], ad);
        }
        float sc[2][4][4] = {};
        #pragma unroll
        for (int mt = 0; mt < 2; mt++)
            #pragma unroll
            for (int jn = 0; jn < 4; jn++) {
                mma_f16(sc[mt][jn], aq[0][mt], &bk[jn][0]);
                mma_f16(sc[mt][jn], aq[1][mt], &bk[jn][2]);
            }
        int jb = kb * 32 + (lane & 3) * 2;
        #pragma unroll
        for (int jn = 0; jn < 4; jn++) {
            int v0 = cjl[jb + jn * 8];
            int v1 = cjl[jb + jn * 8 + 1];
            #pragma unroll
            for (int mt = 0; mt < 2; mt++)
                #pragma unroll
                for (int c = 0; c < 4; c++) {
                    int vv = (c & 1) ? v1 : v0;
                    int rr = mt * 2 + (c >> 1);
                    float s = sc[mt][jn][c] * SCALE_ + rpbh[ibase[rr] - (vv >> 5)];
                    if (!uni && ilab[rr] != (vv & 31)) s -= 100.0f;
                    sc[mt][jn][c] = s;
                }
        }
        float rmax[4] = {-1e30f, -1e30f, -1e30f, -1e30f};
        #pragma unroll
        for (int mt = 0; mt < 2; mt++)
            #pragma unroll
            for (int jn = 0; jn < 4; jn++)
                #pragma unroll
                for (int c = 0; c < 4; c++)
                    rmax[mt * 2 + (c >> 1)] = fmaxf(rmax[mt * 2 + (c >> 1)], sc[mt][jn][c]);
        #pragma unroll
        for (int rr = 0; rr < 4; rr++) {
            rmax[rr] = fmaxf(rmax[rr], __shfl_xor_sync(0xffffffffu, rmax[rr], 1));
            rmax[rr] = fmaxf(rmax[rr], __shfl_xor_sync(0xffffffffu, rmax[rr], 2));
        }
        float corr[4];
        #pragma unroll
        for (int rr = 0; rr < 4; rr++) {
            float nm = fmaxf(m[rr], rmax[rr]);
            corr[rr] = __expf(m[rr] - nm);
            m[rr] = nm;
            sum[rr] *= corr[rr];
        }
        #pragma unroll
        for (int mt = 0; mt < 2; mt++)
            #pragma unroll
            for (int vn = 0; vn < 4; vn++)
                #pragma unroll
                for (int c = 0; c < 4; c++)
                    acc2[mt][vn][c] *= corr[mt * 2 + (c >> 1)];
        uint32_t ap[2][2][4];
        #pragma unroll
        for (int mt = 0; mt < 2; mt++)
            #pragma unroll
            for (int jn = 0; jn < 4; jn++) {
                float p0 = __expf(sc[mt][jn][0] - m[mt * 2]);
                float p1 = __expf(sc[mt][jn][1] - m[mt * 2]);
                float p2 = __expf(sc[mt][jn][2] - m[mt * 2 + 1]);
                float p3 = __expf(sc[mt][jn][3] - m[mt * 2 + 1]);
                sum[mt * 2]     += p0 + p1;
                sum[mt * 2 + 1] += p2 + p3;
                __half2 hA = __floats2half2_rn(p0, p1);
                __half2 hB = __floats2half2_rn(p2, p3);
                ap[jn >> 1][mt][(jn & 1) * 2]     = *(uint32_t*)&hA;
                ap[jn >> 1][mt][(jn & 1) * 2 + 1] = *(uint32_t*)&hB;
            }
        #pragma unroll
        for (int vn = 0; vn < 4; vn++) {
            uint32_t bv[4];
            uint32_t ad = smem_u32(&Vs[(kb * 32 + 8 * (lane >> 3) + (lane & 7)) * 40 + vn * 8]);
            LDM4T(bv[0], bv[1], bv[2], bv[3], ad);
            #pragma unroll
            for (int mt = 0; mt < 2; mt++) {
                mma_f16(acc2[mt][vn], ap[0][mt], &bv[0]);
                mma_f16(acc2[mt][vn], ap[1][mt], &bv[2]);
            }
        }
    }
    float inv[4];
    #pragma unroll
    for (int rr = 0; rr < 4; rr++) {
        sum[rr] += __shfl_xor_sync(0xffffffffu, sum[rr], 1);
        sum[rr] += __shfl_xor_sync(0xffffffffu, sum[rr], 2);
        inv[rr] = 1.0f / sum[rr];
    }
    #pragma unroll
    for (int mt = 0; mt < 2; mt++) {
        size_t row0 = (size_t)(win * 128 + w * 32 + mt * 16 + (lane >> 2));
        #pragma unroll
        for (int vn = 0; vn < 4; vn++) {
            size_t o = row0 * C_ + head * HD_ + vn * 8 + (lane & 3) * 2;
            *(__half2*)&oh[o] = __floats2half2_rn(acc2[mt][vn][0] * inv[mt * 2],
                                                  acc2[mt][vn][1] * inv[mt * 2]);
            size_t o2 = o + 8 * C_;
            *(__half2*)&oh[o2] = __floats2half2_rn(acc2[mt][vn][2] * inv[mt * 2 + 1],
                                                   acc2[mt][vn][3] * inv[mt * 2 + 1]);
        }
    }
}

// ---------------- launch ----------------
#define ARES_SMEM 124416   // 48K (A) + 2*36K (B) + 1.5K (gamma/beta)

extern "C" void kernel_launch(void* const* d_in, const int* in_sizes, int n_in,
                              void* d_out, int out_size) {
    const float* x      = (const float*)d_in[0];
    const float* n1g    = (const float*)d_in[1];
    const float* n1b    = (const float*)d_in[2];
    const float* qkv_w  = (const float*)d_in[3];
    const float* qkv_b  = (const float*)d_in[4];
    const float* rpb    = (const float*)d_in[5];
    const float* proj_w = (const float*)d_in[6];
    const float* proj_b = (const float*)d_in[7];
    const float* n2g    = (const float*)d_in[8];
    const float* n2b    = (const float*)d_in[9];
    const float* fc1_w  = (const float*)d_in[10];
    const float* fc1_b  = (const float*)d_in[11];
    const float* fc2_w  = (const float*)d_in[12];
    const float* fc2_b  = (const float*)d_in[13];
    float* out = (float*)d_out;

    __half *act, *hid, *w, *qkvh;
    float *x2;
    cudaGetSymbolAddress((void**)&act,  g_act);
    cudaGetSymbolAddress((void**)&hid,  g_hid);
    cudaGetSymbolAddress((void**)&w,    g_w);
    cudaGetSymbolAddress((void**)&qkvh, g_qkvh);
    cudaGetSymbolAddress((void**)&x2,   g_x2);

    cudaFuncSetAttribute(k_gemm_ares<0, 6, true>,  cudaFuncAttributeMaxDynamicSharedMemorySize, ARES_SMEM);
    cudaFuncSetAttribute(k_gemm_ares<1, 2, false>, cudaFuncAttributeMaxDynamicSharedMemorySize, ARES_SMEM);
    cudaFuncSetAttribute(k_gemm_ares<2, 8, true>,  cudaFuncAttributeMaxDynamicSharedMemorySize, ARES_SMEM);

    const int OQKV = 0, OPROJ = 110592, OFC1 = 147456, OFC2 = 294912;

    k_wconv_all<<<(442368 + 255)/256, 256>>>(qkv_w, proj_w, fc1_w, fc2_w, w);

    // 1) QKV GEMM with fused LN1 + shift + partition gather -> g_qkvh fp16
    k_gemm_ares<0, 6, true><<<ROWS/128, 256, ARES_SMEM>>>(
        nullptr, x, n1g, n1b, w + OQKV, qkv_b, nullptr, qkvh, nullptr);

    // 2) MMA windowed attention -> act fp16
    k_attn<<<BATCH * NWIN * NH_, 128>>>(qkvh, rpb, act);

    // 3) proj GEMM + reverse + roll + residual -> x2 fp32
    k_gemm_ares<1, 2, false><<<ROWS/128, 256, ARES_SMEM>>>(
        act, nullptr, nullptr, nullptr, w + OPROJ, proj_b, x2, nullptr, x);

    // 4) fc1 GEMM with fused LN2 + GELU -> hid fp16
    k_gemm_ares<2, 8, true><<<ROWS/128, 256, ARES_SMEM>>>(
        nullptr, x2, n2g, n2b, w + OFC1, fc1_b, nullptr, hid, nullptr);

    // 5) fc2 GEMM (4-stage pipelined) + residual -> d_out
    { dim3 g(C_/96, ROWS/128); k_gemm_fc2<<<g, 256>>>(hid, w + OFC2, fc2_b, 768, C_, out, x2); }
}